// round 11
// baseline (speedup 1.0000x reference)
#include <cuda_runtime.h>
#include <cstdint>
#include <math.h>

// ---------------- problem constants ----------------
#define TLEN 1024
#define HID  2048
#define NKH  8
#define NVH  16
#define QKVZN 6144
#define SCALE_Q 0.08838834764831845f   // 128^-0.5

// ---------------- device scratch (no allocation allowed) ----------------
__device__ float g_qkvz[TLEN * QKVZN];
__device__ float g_ba  [TLEN * 32];
__device__ float g_v   [TLEN * 2048];
__device__ float g_qn  [NKH * TLEN * 128];
__device__ float g_kn  [NKH * TLEN * 128];
__device__ float g_scal[NVH * TLEN * 4];
__device__ float g_o   [TLEN * 2048];
__device__ float g_xn  [TLEN * 2048];
__device__ float g_hsr [TLEN * HID];        // tf32-rounded hidden states
__device__ float g_wqr [QKVZN * HID];       // tf32-rounded w_qkvz
__device__ float g_wor [HID * HID];         // tf32-rounded w_out

// ---------------- helpers ----------------
__device__ __forceinline__ float to_tf32(float x) {
    float r;
    asm("cvt.rna.tf32.f32 %0, %1;" : "=f"(r) : "f"(x));
    return r;
}

__device__ __forceinline__ void cp16(void* smem_dst, const void* gmem_src) {
    uint32_t s = (uint32_t)__cvta_generic_to_shared(smem_dst);
    asm volatile("cp.async.cg.shared.global [%0], [%1], 16;\n" :: "r"(s), "l"(gmem_src));
}
#define CP_COMMIT()  asm volatile("cp.async.commit_group;\n")
#define CP_WAIT(n)   asm volatile("cp.async.wait_group %0;\n" :: "n"(n))

__device__ __forceinline__ void mma_tf32(float& d0, float& d1, float& d2, float& d3,
                                         uint32_t a0, uint32_t a1, uint32_t a2, uint32_t a3,
                                         uint32_t b0, uint32_t b1) {
    asm volatile(
        "mma.sync.aligned.m16n8k8.row.col.f32.tf32.tf32.f32 "
        "{%0,%1,%2,%3},{%4,%5,%6,%7},{%8,%9},{%0,%1,%2,%3};"
        : "+f"(d0), "+f"(d1), "+f"(d2), "+f"(d3)
        : "r"(a0), "r"(a1), "r"(a2), "r"(a3), "r"(b0), "r"(b1));
}

// ================= fused pre-pass: ba projection + tf32 rounding =================
#define NH4 (TLEN * HID / 4)
#define NQ4 (QKVZN * HID / 4)
#define NO4 (HID * HID / 4)
#define PREB 4608
__global__ __launch_bounds__(256)
void pre_kernel(const float* __restrict__ hs, const float* __restrict__ wba,
                float* __restrict__ ba_out,
                float4* __restrict__ hsr, float4* __restrict__ wqr,
                float4* __restrict__ wor, const float4* __restrict__ wq4,
                const float4* __restrict__ wo4) {
    const int tid = threadIdx.x;
    if (blockIdx.x < 1024) {
        const int t = blockIdx.x;
        const int n = tid >> 3, s = tid & 7;
        const float4* h4 = (const float4*)(hs + (size_t)t * HID + s * 256);
        const float4* w4 = (const float4*)(wba + (size_t)n * HID + s * 256);
        float acc = 0.f;
#pragma unroll 8
        for (int i = 0; i < 64; i++) {
            float4 a = h4[i], b = w4[i];
            acc += a.x * b.x + a.y * b.y + a.z * b.z + a.w * b.w;
        }
        acc += __shfl_xor_sync(0xffffffffu, acc, 1);
        acc += __shfl_xor_sync(0xffffffffu, acc, 2);
        acc += __shfl_xor_sync(0xffffffffu, acc, 4);
        if (s == 0) ba_out[t * 32 + n] = acc;
    } else {
        const float4* hs4 = (const float4*)hs;
        const int stride = (PREB - 1024) * 256;
        for (int i = (blockIdx.x - 1024) * 256 + tid; i < NH4 + NQ4 + NO4; i += stride) {
            float4 v;
            if (i < NH4) {
                v = hs4[i];
                v.x = to_tf32(v.x); v.y = to_tf32(v.y); v.z = to_tf32(v.z); v.w = to_tf32(v.w);
                hsr[i] = v;
            } else if (i < NH4 + NQ4) {
                v = wq4[i - NH4];
                v.x = to_tf32(v.x); v.y = to_tf32(v.y); v.z = to_tf32(v.z); v.w = to_tf32(v.w);
                wqr[i - NH4] = v;
            } else {
                v = wo4[i - NH4 - NQ4];
                v.x = to_tf32(v.x); v.y = to_tf32(v.y); v.z = to_tf32(v.z); v.w = to_tf32(v.w);
                wor[i - NH4 - NQ4] = v;
            }
        }
    }
}

// ================= tf32 GEMM (cp.async 3-stage, BK=32): C[M,N]=A[M,K]*B[N,K]^T ==
// BM=BN=128, BK=32, 256 threads (8 warps, each 64x32). Inputs pre-rounded rna.
// Stage: A[128][36] then B[128][36] floats (pad-36 rows: 36==4 mod 32, conflict-free).
#define GSTG 3
#define GSTF 9216
__global__ __launch_bounds__(256, 2)
void gemm_tf32_pipe(const float* __restrict__ A, const float* __restrict__ B,
                    float* __restrict__ C, int N, int K) {
    extern __shared__ float sm[];   // GSTG * GSTF floats = 108KB

    const int tid  = threadIdx.x;
    const int warp = tid >> 5, lane = tid & 31;
    const int wm = warp & 1, wn = warp >> 1;
    const int bm = blockIdx.y * 128, bn = blockIdx.x * 128;
    const int row = tid >> 1, c0 = (tid & 1) * 16;

    const float* Ab = A + (size_t)bm * K;
    const float* Bb = B + (size_t)bn * K;
    const int nk = K >> 5;   // BK=32 tiles

    float acc[4][4][4];
#pragma unroll
    for (int i = 0; i < 4; i++)
#pragma unroll
        for (int j = 0; j < 4; j++)
#pragma unroll
            for (int l = 0; l < 4; l++) acc[i][j][l] = 0.f;

    auto preload = [&](int kt) {
        const int k0 = (kt << 5) + c0;
        float* st = sm + (kt % 3) * GSTF;
        const float* pa = Ab + (size_t)row * K + k0;
        float* sa = st + row * 36 + c0;
        cp16(sa,      pa);
        cp16(sa + 4,  pa + 4);
        cp16(sa + 8,  pa + 8);
        cp16(sa + 12, pa + 12);
        const float* pb = Bb + (size_t)row * K + k0;
        float* sb = st + 4608 + row * 36 + c0;
        cp16(sb,      pb);
        cp16(sb + 4,  pb + 4);
        cp16(sb + 8,  pb + 8);
        cp16(sb + 12, pb + 12);
    };

    preload(0); CP_COMMIT();
    preload(1); CP_COMMIT();

    for (int kt = 0; kt < nk; kt++) {
        CP_WAIT(1);
        __syncthreads();
        const float* sAb = sm + (kt % 3) * GSTF;
        const float* sBb = sAb + 4608;
#pragma unroll
        for (int ks = 0; ks < 4; ks++) {
            uint32_t af[4][4];
#pragma unroll
            for (int mt = 0; mt < 4; mt++) {
                const float* p = sAb + (wm * 64 + mt * 16 + (lane >> 2)) * 36 + ks * 8 + (lane & 3);
                af[mt][0] = __float_as_uint(p[0]);
                af[mt][1] = __float_as_uint(p[8 * 36]);
                af[mt][2] = __float_as_uint(p[4]);
                af[mt][3] = __float_as_uint(p[8 * 36 + 4]);
            }
            uint32_t bf[4][2];
#pragma unroll
            for (int nt = 0; nt < 4; nt++) {
                const float* p = sBb + (wn * 32 + nt * 8 + (lane >> 2)) * 36 + ks * 8 + (lane & 3);
                bf[nt][0] = __float_as_uint(p[0]);
                bf[nt][1] = __float_as_uint(p[4]);
            }
#pragma unroll
            for (int mt = 0; mt < 4; mt++)
#pragma unroll
                for (int nt = 0; nt < 4; nt++)
                    mma_tf32(acc[mt][nt][0], acc[mt][nt][1], acc[mt][nt][2], acc[mt][nt][3],
                             af[mt][0], af[mt][1], af[mt][2], af[mt][3],
                             bf[nt][0], bf[nt][1]);
        }
        if (kt + 2 < nk) preload(kt + 2);
        CP_COMMIT();
    }

#pragma unroll
    for (int mt = 0; mt < 4; mt++) {
#pragma unroll
        for (int nt = 0; nt < 4; nt++) {
            int r = bm + wm * 64 + mt * 16 + (lane >> 2);
            int col = bn + wn * 32 + nt * 8 + (lane & 3) * 2;
            C[(size_t)r * N + col]           = acc[mt][nt][0];
            C[(size_t)r * N + col + 1]       = acc[mt][nt][1];
            C[(size_t)(r + 8) * N + col]     = acc[mt][nt][2];
            C[(size_t)(r + 8) * N + col + 1] = acc[mt][nt][3];
        }
    }
}

// ================= fused conv1d+silu + l2-norm + gates =================
__global__ __launch_bounds__(128)
void convprep_kernel(const float* __restrict__ qkvz, const float* __restrict__ convw,
                     const float* __restrict__ gba, const float* __restrict__ A_log,
                     const float* __restrict__ dt_bias,
                     float* __restrict__ gqn, float* __restrict__ gkn,
                     float* __restrict__ gv, float* __restrict__ gscal) {
    const int t = blockIdx.x, kh = blockIdx.y, i = threadIdx.x;
    __shared__ float red[4];
    const int base = kh * 768;

    float xq[4], xk[4], xv0[4], xv1[4];
#pragma unroll
    for (int tau = 0; tau < 4; tau++) {
        const int tt = t - 3 + tau;
        const bool ok = (tt >= 0);
        const float* r = qkvz + (size_t)(ok ? tt : 0) * QKVZN + base;
        xq[tau]  = ok ? r[i]       : 0.f;
        xk[tau]  = ok ? r[128 + i] : 0.f;
        xv0[tau] = ok ? r[256 + i] : 0.f;
        xv1[tau] = ok ? r[384 + i] : 0.f;
    }
    const float4 wq  = *(const float4*)(convw + (size_t)(kh * 128 + i) * 4);
    const float4 wk  = *(const float4*)(convw + (size_t)(1024 + kh * 128 + i) * 4);
    const float4 wv0 = *(const float4*)(convw + (size_t)(2048 + (2 * kh) * 128 + i) * 4);
    const float4 wv1 = *(const float4*)(convw + (size_t)(2048 + (2 * kh + 1) * 128 + i) * 4);

    float q  = xq[0] * wq.x + xq[1] * wq.y + xq[2] * wq.z + xq[3] * wq.w;
    float k  = xk[0] * wk.x + xk[1] * wk.y + xk[2] * wk.z + xk[3] * wk.w;
    float v0 = xv0[0] * wv0.x + xv0[1] * wv0.y + xv0[2] * wv0.z + xv0[3] * wv0.w;
    float v1 = xv1[0] * wv1.x + xv1[1] * wv1.y + xv1[2] * wv1.z + xv1[3] * wv1.w;
    q  = q  / (1.f + expf(-q));
    k  = k  / (1.f + expf(-k));
    v0 = v0 / (1.f + expf(-v0));
    v1 = v1 / (1.f + expf(-v1));

    gv[(size_t)t * 2048 + (2 * kh) * 128 + i]     = v0;
    gv[(size_t)t * 2048 + (2 * kh + 1) * 128 + i] = v1;

    float v, s_qq, s_kk, s_qk;

    v = q * q;
#pragma unroll
    for (int m = 16; m; m >>= 1) v += __shfl_xor_sync(0xffffffffu, v, m);
    if ((i & 31) == 0) red[i >> 5] = v;
    __syncthreads();
    s_qq = red[0] + red[1] + red[2] + red[3];
    __syncthreads();

    v = k * k;
#pragma unroll
    for (int m = 16; m; m >>= 1) v += __shfl_xor_sync(0xffffffffu, v, m);
    if ((i & 31) == 0) red[i >> 5] = v;
    __syncthreads();
    s_kk = red[0] + red[1] + red[2] + red[3];
    __syncthreads();

    const float qn = q * rsqrtf(s_qq + 1e-6f) * SCALE_Q;
    const float kn = k * rsqrtf(s_kk + 1e-6f);
    gqn[((size_t)kh * TLEN + t) * 128 + i] = qn;
    gkn[((size_t)kh * TLEN + t) * 128 + i] = kn;

    v = qn * kn;
#pragma unroll
    for (int m = 16; m; m >>= 1) v += __shfl_xor_sync(0xffffffffu, v, m);
    if ((i & 31) == 0) red[i >> 5] = v;
    __syncthreads();
    s_qk = red[0] + red[1] + red[2] + red[3];

    if (i < 2) {
        const int vh = kh * 2 + i;
        const float b = gba[t * 32 + kh * 4 + i];
        const float a = gba[t * 32 + kh * 4 + 2 + i];
        const float beta = 1.f / (1.f + expf(-b));
        const float x = a + dt_bias[vh];
        const float sp = (x > 20.f) ? x : log1pf(expf(x));
        const float g = -expf(A_log[vh]) * sp;
        float4 sc;
        sc.x = expf(g); sc.y = beta; sc.z = s_qk; sc.w = 0.f;
        *(float4*)(gscal + ((size_t)vh * TLEN + t) * 4) = sc;
    }
}

// ================= gated delta-rule scan (R9 proven config) =================
// grid (8 vblocks, 16 heads), 256 threads = 16 kgroups x 16 vcols
// (2 warps per SMSP). 16-slot ring, warp-pair per slot prefetch, 4-step cadence.
__global__ __launch_bounds__(256, 1)
void scan_kernel(const float* __restrict__ gqn, const float* __restrict__ gkn,
                 const float* __restrict__ gv, const float* __restrict__ gscal,
                 float* __restrict__ go) {
    const int vb = blockIdx.x;
    const int vh = blockIdx.y;
    const int kh = vh >> 1;
    const int tid = threadIdx.x;
    const int kg = tid & 15;      // k group (8 k-slots each)
    const int vc = tid >> 4;      // v col within block (0..15)

    __shared__ __align__(16) float ring[16][276];  // k[128], q[128], v[16], scal[4]

    const float* kbase = gkn + (size_t)kh * TLEN * 128;
    const float* qbase = gqn + (size_t)kh * TLEN * 128;
    const float* vbase = gv + vh * 128 + vb * 16;
    const float* sbase = gscal + (size_t)vh * TLEN * 4;

    float S[8];
#pragma unroll
    for (int i = 0; i < 8; i++) S[i] = 0.f;

    const int pw = tid >> 5, pl = tid & 31;   // 8 warps: pair (2w,2w+1) owns slot t0+w

    auto prefetch4 = [&](int t0) {
        const int tt = t0 + (pw >> 1);
        if (tt < TLEN) {
            float* sl = ring[tt & 15];
            if ((pw & 1) == 0) {
                cp16(sl + pl * 4, kbase + (size_t)tt * 128 + pl * 4);
                if (pl < 4) cp16(sl + 256 + pl * 4, vbase + (size_t)tt * 2048 + pl * 4);
                if (pl == 4) cp16(sl + 272, sbase + (size_t)tt * 4);
            } else {
                cp16(sl + 128 + pl * 4, qbase + (size_t)tt * 128 + pl * 4);
            }
        }
        CP_COMMIT();
    };

    prefetch4(0);
    prefetch4(4);
    prefetch4(8);

    const int obase = vh * 128 + vb * 16 + vc;

    for (int t = 0; t < TLEN; t += 4) {
        CP_WAIT(2);
        __syncthreads();
        prefetch4(t + 12);
#pragma unroll
        for (int u = 0; u < 4; u++) {
            const int tt = t + u;
            const float* sl = ring[tt & 15];
            const float4* kp = (const float4*)(sl + kg * 8);
            const float4* qp = (const float4*)(sl + 128 + kg * 8);
            const float4 k0 = kp[0], k1 = kp[1];
            const float4 q0 = qp[0], q1 = qp[1];

            const float4 sc = *(const float4*)(sl + 272);
            const float eg = sc.x, beta = sc.y, qk = sc.z;
            const float vt = sl[256 + vc];
            const float vtb = vt * beta;
            const float negb = -eg * beta;

            float r1a, r1b, r2a, r2b;
            r1a = k0.x * S[0];               r2a = q0.x * S[0];
            r1b = k1.x * S[4];               r2b = q1.x * S[4];
            r1a = fmaf(k0.y, S[1], r1a);     r2a = fmaf(q0.y, S[1], r2a);
            r1b = fmaf(k1.y, S[5], r1b);     r2b = fmaf(q1.y, S[5], r2b);
            r1a = fmaf(k0.z, S[2], r1a);     r2a = fmaf(q0.z, S[2], r2a);
            r1b = fmaf(k1.z, S[6], r1b);     r2b = fmaf(q1.z, S[6], r2b);
            r1a = fmaf(k0.w, S[3], r1a);     r2a = fmaf(q0.w, S[3], r2a);
            r1b = fmaf(k1.w, S[7], r1b);     r2b = fmaf(q1.w, S[7], r2b);

            float r1 = r1a + r1b;
            float r2 = r2a + r2b;

            r1 += __shfl_xor_sync(0xffffffffu, r1, 1);
            r2 += __shfl_xor_sync(0xffffffffu, r2, 1);
            r1 += __shfl_xor_sync(0xffffffffu, r1, 2);
            r2 += __shfl_xor_sync(0xffffffffu, r2, 2);
            r1 += __shfl_xor_sync(0xffffffffu, r1, 4);
            r2 += __shfl_xor_sync(0xffffffffu, r2, 4);
            r1 += __shfl_xor_sync(0xffffffffu, r1, 8);
            r2 += __shfl_xor_sync(0xffffffffu, r2, 8);

            float eS[8];
#pragma unroll
            for (int j = 0; j < 8; j++) eS[j] = eg * S[j];

            const float delta = fmaf(negb, r1, vtb);
            if (kg == 0) go[(size_t)tt * 2048 + obase] = fmaf(eg, r2, qk * delta);

            S[0] = fmaf(k0.x, delta, eS[0]);
            S[1] = fmaf(k0.y, delta, eS[1]);
            S[2] = fmaf(k0.z, delta, eS[2]);
            S[3] = fmaf(k0.w, delta, eS[3]);
            S[4] = fmaf(k1.x, delta, eS[4]);
            S[5] = fmaf(k1.y, delta, eS[5]);
            S[6] = fmaf(k1.z, delta, eS[6]);
            S[7] = fmaf(k1.w, delta, eS[7]);
        }
    }
}

// ================= gated RMSNorm (emits tf32-rounded xn) =================
__global__ __launch_bounds__(128)
void rmsnorm_kernel(const float* __restrict__ go, const float* __restrict__ qkvz,
                    const float* __restrict__ nw, float* __restrict__ gxn) {
    const int t = blockIdx.x, vh = blockIdx.y, i = threadIdx.x;
    __shared__ float red[4];
    const float o = go[(size_t)t * 2048 + vh * 128 + i];
    const float z = qkvz[(size_t)t * QKVZN + (vh >> 1) * 768 + 512 + (vh & 1) * 128 + i];
    const float xf = o * (z / (1.f + expf(-z)));
    float v = xf * xf;
#pragma unroll
    for (int m = 16; m; m >>= 1) v += __shfl_xor_sync(0xffffffffu, v, m);
    if ((i & 31) == 0) red[i >> 5] = v;
    __syncthreads();
    const float s = red[0] + red[1] + red[2] + red[3];
    gxn[(size_t)t * 2048 + vh * 128 + i] =
        to_tf32(xf * rsqrtf(s * (1.f / 128.f) + 1e-6f) * nw[i]);
}

// ================= launch =================
extern "C" void kernel_launch(void* const* d_in, const int* in_sizes, int n_in,
                              void* d_out, int out_size) {
    const float* hs      = (const float*)d_in[0];
    const float* w_qkvz  = (const float*)d_in[1];
    const float* w_ba    = (const float*)d_in[2];
    const float* conv_w  = (const float*)d_in[3];
    const float* dt_bias = (const float*)d_in[4];
    const float* A_log   = (const float*)d_in[5];
    const float* norm_w  = (const float*)d_in[6];
    const float* w_out   = (const float*)d_in[7];
    float* out = (float*)d_out;

    float *p_qkvz, *p_ba, *p_v, *p_qn, *p_kn, *p_scal, *p_o, *p_xn;
    float *p_hsr, *p_wqr, *p_wor;
    cudaGetSymbolAddress((void**)&p_qkvz, g_qkvz);
    cudaGetSymbolAddress((void**)&p_ba,   g_ba);
    cudaGetSymbolAddress((void**)&p_v,    g_v);
    cudaGetSymbolAddress((void**)&p_qn,   g_qn);
    cudaGetSymbolAddress((void**)&p_kn,   g_kn);
    cudaGetSymbolAddress((void**)&p_scal, g_scal);
    cudaGetSymbolAddress((void**)&p_o,    g_o);
    cudaGetSymbolAddress((void**)&p_xn,   g_xn);
    cudaGetSymbolAddress((void**)&p_hsr,  g_hsr);
    cudaGetSymbolAddress((void**)&p_wqr,  g_wqr);
    cudaGetSymbolAddress((void**)&p_wor,  g_wor);

    static int smem_set = 0;
    if (!smem_set) {
        cudaFuncSetAttribute(gemm_tf32_pipe, cudaFuncAttributeMaxDynamicSharedMemorySize,
                             GSTG * GSTF * 4);
        smem_set = 1;
    }

    // launch 0: ba projection + tf32 rounding (fused)
    pre_kernel<<<PREB, 256>>>(hs, w_ba, p_ba, (float4*)p_hsr, (float4*)p_wqr,
                              (float4*)p_wor, (const float4*)w_qkvz, (const float4*)w_out);
    // launch 1: qkvz projection [1024,6144]
    gemm_tf32_pipe<<<dim3(QKVZN / 128, TLEN / 128), 256, GSTG * GSTF * 4>>>(
        p_hsr, p_wqr, p_qkvz, QKVZN, HID);
    // launch 2: fused conv + silu + norms + gates
    convprep_kernel<<<dim3(TLEN, NKH), 128>>>(p_qkvz, conv_w, p_ba, A_log, dt_bias,
                                              p_qn, p_kn, p_v, p_scal);
    // launch 3: delta-rule scan  (ncu captures launch index 3)
    scan_kernel<<<dim3(8, NVH), 256>>>(p_qn, p_kn, p_v, p_scal, p_o);
    // launch 4: gated rmsnorm (tf32-rounded output)
    rmsnorm_kernel<<<dim3(TLEN, NVH), 128>>>(p_o, p_qkvz, norm_w, p_xn);
    // launch 5: output projection [1024,2048]
    gemm_tf32_pipe<<<dim3(HID / 128, TLEN / 128), 256, GSTG * GSTF * 4>>>(
        p_xn, p_wor, out, HID, HID);
}

// round 12
// speedup vs baseline: 1.0848x; 1.0848x over previous
#include <cuda_runtime.h>
#include <cstdint>
#include <math.h>

// ---------------- problem constants ----------------
#define TLEN 1024
#define HID  2048
#define NKH  8
#define NVH  16
#define QKVZN 6144
#define SCALE_Q 0.08838834764831845f   // 128^-0.5

// ---------------- device scratch (no allocation allowed) ----------------
__device__ float g_qkvz[TLEN * QKVZN];
__device__ float g_ba  [TLEN * 32];
__device__ float g_v   [TLEN * 2048];
__device__ float g_qn  [NKH * TLEN * 128];
__device__ float g_kn  [NKH * TLEN * 128];
__device__ float g_scal[NVH * TLEN * 4];
__device__ float g_cross[NKH * 512 * 4];    // per (kh, pair): {k1.k0, q1.k0, 0, 0}
__device__ float g_o   [TLEN * 2048];
__device__ float g_xn  [TLEN * 2048];
__device__ float g_hsr [TLEN * HID];        // tf32-rounded hidden states
__device__ float g_wqr [QKVZN * HID];       // tf32-rounded w_qkvz
__device__ float g_wor [HID * HID];         // tf32-rounded w_out

// ---------------- helpers ----------------
__device__ __forceinline__ float to_tf32(float x) {
    float r;
    asm("cvt.rna.tf32.f32 %0, %1;" : "=f"(r) : "f"(x));
    return r;
}

__device__ __forceinline__ void cp16(void* smem_dst, const void* gmem_src) {
    uint32_t s = (uint32_t)__cvta_generic_to_shared(smem_dst);
    asm volatile("cp.async.cg.shared.global [%0], [%1], 16;\n" :: "r"(s), "l"(gmem_src));
}
#define CP_COMMIT()  asm volatile("cp.async.commit_group;\n")
#define CP_WAIT(n)   asm volatile("cp.async.wait_group %0;\n" :: "n"(n))

__device__ __forceinline__ void mma_tf32(float& d0, float& d1, float& d2, float& d3,
                                         uint32_t a0, uint32_t a1, uint32_t a2, uint32_t a3,
                                         uint32_t b0, uint32_t b1) {
    asm volatile(
        "mma.sync.aligned.m16n8k8.row.col.f32.tf32.tf32.f32 "
        "{%0,%1,%2,%3},{%4,%5,%6,%7},{%8,%9},{%0,%1,%2,%3};"
        : "+f"(d0), "+f"(d1), "+f"(d2), "+f"(d3)
        : "r"(a0), "r"(a1), "r"(a2), "r"(a3), "r"(b0), "r"(b1));
}

// ================= fused pre-pass: ba projection + tf32 rounding =================
#define NH4 (TLEN * HID / 4)
#define NQ4 (QKVZN * HID / 4)
#define NO4 (HID * HID / 4)
#define PREB 4608
__global__ __launch_bounds__(256)
void pre_kernel(const float* __restrict__ hs, const float* __restrict__ wba,
                float* __restrict__ ba_out,
                float4* __restrict__ hsr, float4* __restrict__ wqr,
                float4* __restrict__ wor, const float4* __restrict__ wq4,
                const float4* __restrict__ wo4) {
    const int tid = threadIdx.x;
    if (blockIdx.x < 1024) {
        const int t = blockIdx.x;
        const int n = tid >> 3, s = tid & 7;
        const float4* h4 = (const float4*)(hs + (size_t)t * HID + s * 256);
        const float4* w4 = (const float4*)(wba + (size_t)n * HID + s * 256);
        float acc = 0.f;
#pragma unroll 8
        for (int i = 0; i < 64; i++) {
            float4 a = h4[i], b = w4[i];
            acc += a.x * b.x + a.y * b.y + a.z * b.z + a.w * b.w;
        }
        acc += __shfl_xor_sync(0xffffffffu, acc, 1);
        acc += __shfl_xor_sync(0xffffffffu, acc, 2);
        acc += __shfl_xor_sync(0xffffffffu, acc, 4);
        if (s == 0) ba_out[t * 32 + n] = acc;
    } else {
        const float4* hs4 = (const float4*)hs;
        const int stride = (PREB - 1024) * 256;
        for (int i = (blockIdx.x - 1024) * 256 + tid; i < NH4 + NQ4 + NO4; i += stride) {
            float4 v;
            if (i < NH4) {
                v = hs4[i];
                v.x = to_tf32(v.x); v.y = to_tf32(v.y); v.z = to_tf32(v.z); v.w = to_tf32(v.w);
                hsr[i] = v;
            } else if (i < NH4 + NQ4) {
                v = wq4[i - NH4];
                v.x = to_tf32(v.x); v.y = to_tf32(v.y); v.z = to_tf32(v.z); v.w = to_tf32(v.w);
                wqr[i - NH4] = v;
            } else {
                v = wo4[i - NH4 - NQ4];
                v.x = to_tf32(v.x); v.y = to_tf32(v.y); v.z = to_tf32(v.z); v.w = to_tf32(v.w);
                wor[i - NH4 - NQ4] = v;
            }
        }
    }
}

// ================= tf32 GEMM (cp.async 4-stage, BK=16) — R9 proven =================
#define GSTG 4
#define GSTF 5120
__global__ __launch_bounds__(256, 2)
void gemm_tf32_pipe(const float* __restrict__ A, const float* __restrict__ B,
                    float* __restrict__ C, int N, int K) {
    extern __shared__ float sm[];   // GSTG * GSTF floats = 80KB

    const int tid  = threadIdx.x;
    const int warp = tid >> 5, lane = tid & 31;
    const int wm = warp & 1, wn = warp >> 1;
    const int bm = blockIdx.y * 128, bn = blockIdx.x * 128;
    const int r0 = tid >> 2, c4 = tid & 3;

    const float* Ab = A + (size_t)bm * K;
    const float* Bb = B + (size_t)bn * K;
    const int nk = K >> 4;

    float acc[4][4][4];
#pragma unroll
    for (int i = 0; i < 4; i++)
#pragma unroll
        for (int j = 0; j < 4; j++)
#pragma unroll
            for (int l = 0; l < 4; l++) acc[i][j][l] = 0.f;

    auto preload = [&](int kt) {
        const int k0 = (kt << 4) + c4 * 4;
        float* st = sm + (kt & 3) * GSTF;
        cp16(st + r0 * 20 + c4 * 4,                Ab + (size_t)r0 * K + k0);
        cp16(st + (r0 + 64) * 20 + c4 * 4,         Ab + (size_t)(r0 + 64) * K + k0);
        cp16(st + 2560 + r0 * 20 + c4 * 4,         Bb + (size_t)r0 * K + k0);
        cp16(st + 2560 + (r0 + 64) * 20 + c4 * 4,  Bb + (size_t)(r0 + 64) * K + k0);
    };

    preload(0); CP_COMMIT();
    preload(1); CP_COMMIT();
    preload(2); CP_COMMIT();

    for (int kt = 0; kt < nk; kt++) {
        CP_WAIT(2);
        __syncthreads();
        const float* sAb = sm + (kt & 3) * GSTF;
        const float* sBb = sAb + 2560;
#pragma unroll
        for (int ks = 0; ks < 2; ks++) {
            uint32_t af[4][4];
#pragma unroll
            for (int mt = 0; mt < 4; mt++) {
                const float* p = sAb + (wm * 64 + mt * 16 + (lane >> 2)) * 20 + ks * 8 + (lane & 3);
                af[mt][0] = __float_as_uint(p[0]);
                af[mt][1] = __float_as_uint(p[8 * 20]);
                af[mt][2] = __float_as_uint(p[4]);
                af[mt][3] = __float_as_uint(p[8 * 20 + 4]);
            }
            uint32_t bf[4][2];
#pragma unroll
            for (int nt = 0; nt < 4; nt++) {
                const float* p = sBb + (wn * 32 + nt * 8 + (lane >> 2)) * 20 + ks * 8 + (lane & 3);
                bf[nt][0] = __float_as_uint(p[0]);
                bf[nt][1] = __float_as_uint(p[4]);
            }
#pragma unroll
            for (int mt = 0; mt < 4; mt++)
#pragma unroll
                for (int nt = 0; nt < 4; nt++)
                    mma_tf32(acc[mt][nt][0], acc[mt][nt][1], acc[mt][nt][2], acc[mt][nt][3],
                             af[mt][0], af[mt][1], af[mt][2], af[mt][3],
                             bf[nt][0], bf[nt][1]);
        }
        if (kt + 3 < nk) preload(kt + 3);
        CP_COMMIT();
    }

#pragma unroll
    for (int mt = 0; mt < 4; mt++) {
#pragma unroll
        for (int nt = 0; nt < 4; nt++) {
            int row = bm + wm * 64 + mt * 16 + (lane >> 2);
            int col = bn + wn * 32 + nt * 8 + (lane & 3) * 2;
            C[(size_t)row * N + col]           = acc[mt][nt][0];
            C[(size_t)row * N + col + 1]       = acc[mt][nt][1];
            C[(size_t)(row + 8) * N + col]     = acc[mt][nt][2];
            C[(size_t)(row + 8) * N + col + 1] = acc[mt][nt][3];
        }
    }
}

// ================= fused conv1d+silu + l2-norm + gates + cross-dots =================
// grid (1024, 8), 128 threads. Odd-t blocks additionally recompute kn_{t-1}
// (bit-identical) and emit cross dots {kn_t.kn_{t-1}, qn_t.kn_{t-1}}.
__global__ __launch_bounds__(128)
void convprep_kernel(const float* __restrict__ qkvz, const float* __restrict__ convw,
                     const float* __restrict__ gba, const float* __restrict__ A_log,
                     const float* __restrict__ dt_bias,
                     float* __restrict__ gqn, float* __restrict__ gkn,
                     float* __restrict__ gv, float* __restrict__ gscal,
                     float* __restrict__ gcross) {
    const int t = blockIdx.x, kh = blockIdx.y, i = threadIdx.x;
    __shared__ float red[4];
    const int base = kh * 768;

    float xq[4], xk[4], xv0[4], xv1[4];
#pragma unroll
    for (int tau = 0; tau < 4; tau++) {
        const int tt = t - 3 + tau;
        const bool ok = (tt >= 0);
        const float* r = qkvz + (size_t)(ok ? tt : 0) * QKVZN + base;
        xq[tau]  = ok ? r[i]       : 0.f;
        xk[tau]  = ok ? r[128 + i] : 0.f;
        xv0[tau] = ok ? r[256 + i] : 0.f;
        xv1[tau] = ok ? r[384 + i] : 0.f;
    }
    const float4 wq  = *(const float4*)(convw + (size_t)(kh * 128 + i) * 4);
    const float4 wk  = *(const float4*)(convw + (size_t)(1024 + kh * 128 + i) * 4);
    const float4 wv0 = *(const float4*)(convw + (size_t)(2048 + (2 * kh) * 128 + i) * 4);
    const float4 wv1 = *(const float4*)(convw + (size_t)(2048 + (2 * kh + 1) * 128 + i) * 4);

    float q  = xq[0] * wq.x + xq[1] * wq.y + xq[2] * wq.z + xq[3] * wq.w;
    float k  = xk[0] * wk.x + xk[1] * wk.y + xk[2] * wk.z + xk[3] * wk.w;
    float v0 = xv0[0] * wv0.x + xv0[1] * wv0.y + xv0[2] * wv0.z + xv0[3] * wv0.w;
    float v1 = xv1[0] * wv1.x + xv1[1] * wv1.y + xv1[2] * wv1.z + xv1[3] * wv1.w;
    q  = q  / (1.f + expf(-q));
    k  = k  / (1.f + expf(-k));
    v0 = v0 / (1.f + expf(-v0));
    v1 = v1 / (1.f + expf(-v1));

    gv[(size_t)t * 2048 + (2 * kh) * 128 + i]     = v0;
    gv[(size_t)t * 2048 + (2 * kh + 1) * 128 + i] = v1;

    float v, s_qq, s_kk, s_qk;

    v = q * q;
#pragma unroll
    for (int m = 16; m; m >>= 1) v += __shfl_xor_sync(0xffffffffu, v, m);
    if ((i & 31) == 0) red[i >> 5] = v;
    __syncthreads();
    s_qq = red[0] + red[1] + red[2] + red[3];
    __syncthreads();

    v = k * k;
#pragma unroll
    for (int m = 16; m; m >>= 1) v += __shfl_xor_sync(0xffffffffu, v, m);
    if ((i & 31) == 0) red[i >> 5] = v;
    __syncthreads();
    s_kk = red[0] + red[1] + red[2] + red[3];
    __syncthreads();

    const float qn = q * rsqrtf(s_qq + 1e-6f) * SCALE_Q;
    const float kn = k * rsqrtf(s_kk + 1e-6f);
    gqn[((size_t)kh * TLEN + t) * 128 + i] = qn;
    gkn[((size_t)kh * TLEN + t) * 128 + i] = kn;

    v = qn * kn;
#pragma unroll
    for (int m = 16; m; m >>= 1) v += __shfl_xor_sync(0xffffffffu, v, m);
    if ((i & 31) == 0) red[i >> 5] = v;
    __syncthreads();
    s_qk = red[0] + red[1] + red[2] + red[3];

    if (i < 2) {
        const int vh = kh * 2 + i;
        const float b = gba[t * 32 + kh * 4 + i];
        const float a = gba[t * 32 + kh * 4 + 2 + i];
        const float beta = 1.f / (1.f + expf(-b));
        const float x = a + dt_bias[vh];
        const float sp = (x > 20.f) ? x : log1pf(expf(x));
        const float g = -expf(A_log[vh]) * sp;
        float4 sc;
        sc.x = expf(g); sc.y = beta; sc.z = s_qk; sc.w = 0.f;
        *(float4*)(gscal + ((size_t)vh * TLEN + t) * 4) = sc;
    }

    // ---- odd-t blocks: cross dots with step t-1 ----
    if (t & 1) {
        const int tm4 = t - 4;
        const float xkm = (tm4 >= 0) ? qkvz[(size_t)tm4 * QKVZN + base + 128 + i] : 0.f;
        float kp = xkm * wk.x + xk[0] * wk.y + xk[1] * wk.z + xk[2] * wk.w;
        kp = kp / (1.f + expf(-kp));

        __syncthreads();
        v = kp * kp;
#pragma unroll
        for (int m = 16; m; m >>= 1) v += __shfl_xor_sync(0xffffffffu, v, m);
        if ((i & 31) == 0) red[i >> 5] = v;
        __syncthreads();
        const float s_kkp = red[0] + red[1] + red[2] + red[3];
        __syncthreads();
        const float knp = kp * rsqrtf(s_kkp + 1e-6f);

        v = kn * knp;
#pragma unroll
        for (int m = 16; m; m >>= 1) v += __shfl_xor_sync(0xffffffffu, v, m);
        if ((i & 31) == 0) red[i >> 5] = v;
        __syncthreads();
        const float s_kk01 = red[0] + red[1] + red[2] + red[3];
        __syncthreads();

        v = qn * knp;
#pragma unroll
        for (int m = 16; m; m >>= 1) v += __shfl_xor_sync(0xffffffffu, v, m);
        if ((i & 31) == 0) red[i >> 5] = v;
        __syncthreads();
        const float s_qk10 = red[0] + red[1] + red[2] + red[3];

        if (i == 0) {
            float4 c;
            c.x = s_kk01; c.y = s_qk10; c.z = 0.f; c.w = 0.f;
            *(float4*)(gcross + ((size_t)kh * 512 + (t >> 1)) * 4) = c;
        }
    }
}

// ================= gated delta-rule scan (2-step fused) =================
// grid (8 vblocks, 16 heads), 256 threads = 16 kgroups x 16 vcols.
// One butterfly batch per 2 steps using precomputed cross dots.
__global__ __launch_bounds__(256, 1)
void scan_kernel(const float* __restrict__ gqn, const float* __restrict__ gkn,
                 const float* __restrict__ gv, const float* __restrict__ gscal,
                 const float* __restrict__ gcross, float* __restrict__ go) {
    const int vb = blockIdx.x;
    const int vh = blockIdx.y;
    const int kh = vh >> 1;
    const int tid = threadIdx.x;
    const int kg = tid & 15;      // k group (8 k-slots each)
    const int vc = tid >> 4;      // v col within block (0..15)

    __shared__ __align__(16) float ring[16][280];  // k[128],q[128],v[16],scal[4],cross[4]

    const float* kbase = gkn + (size_t)kh * TLEN * 128;
    const float* qbase = gqn + (size_t)kh * TLEN * 128;
    const float* vbase = gv + vh * 128 + vb * 16;
    const float* sbase = gscal + (size_t)vh * TLEN * 4;
    const float* cbase = gcross + (size_t)kh * 512 * 4;

    float S[8];
#pragma unroll
    for (int i = 0; i < 8; i++) S[i] = 0.f;

    const int pw = tid >> 5, pl = tid & 31;   // 8 warps: pair (2w,2w+1) owns slot t0+w

    auto prefetch4 = [&](int t0) {
        const int tt = t0 + (pw >> 1);
        if (tt < TLEN) {
            float* sl = ring[tt & 15];
            if ((pw & 1) == 0) {
                cp16(sl + pl * 4, kbase + (size_t)tt * 128 + pl * 4);
                if (pl < 4) cp16(sl + 256 + pl * 4, vbase + (size_t)tt * 2048 + pl * 4);
                if (pl == 4) cp16(sl + 272, sbase + (size_t)tt * 4);
                if (pl == 5 && (tt & 1)) cp16(sl + 276, cbase + (size_t)(tt >> 1) * 4);
            } else {
                cp16(sl + 128 + pl * 4, qbase + (size_t)tt * 128 + pl * 4);
            }
        }
        CP_COMMIT();
    };

    prefetch4(0);
    prefetch4(4);
    prefetch4(8);

    const int obase = vh * 128 + vb * 16 + vc;

    for (int t = 0; t < TLEN; t += 4) {
        CP_WAIT(2);
        __syncthreads();
        prefetch4(t + 12);
#pragma unroll
        for (int u = 0; u < 4; u += 2) {
            const int tt = t + u;
            const float* s0 = ring[tt & 15];
            const float* s1 = ring[(tt + 1) & 15];

            const float4 k0a = *(const float4*)(s0 + kg * 8);
            const float4 k0b = *(const float4*)(s0 + kg * 8 + 4);
            const float4 q0a = *(const float4*)(s0 + 128 + kg * 8);
            const float4 q0b = *(const float4*)(s0 + 128 + kg * 8 + 4);
            const float4 k1a = *(const float4*)(s1 + kg * 8);
            const float4 k1b = *(const float4*)(s1 + kg * 8 + 4);
            const float4 q1a = *(const float4*)(s1 + 128 + kg * 8);
            const float4 q1b = *(const float4*)(s1 + 128 + kg * 8 + 4);

            const float4 g0 = *(const float4*)(s0 + 272);   // eg0, b0, qk0
            const float4 g1 = *(const float4*)(s1 + 272);   // eg1, b1, qk1
            const float kk01 = s1[276], qk10 = s1[277];
            const float v0 = s0[256 + vc], v1 = s1[256 + vc];

            // 4 dots against pre-decay S, 2-way split chains
            float c1a, c1b, c2a, c2b, c3a, c3b, c4a, c4b;
            c1a = k0a.x * S[0];            c1b = k0b.x * S[4];
            c2a = q0a.x * S[0];            c2b = q0b.x * S[4];
            c3a = k1a.x * S[0];            c3b = k1b.x * S[4];
            c4a = q1a.x * S[0];            c4b = q1b.x * S[4];
            c1a = fmaf(k0a.y, S[1], c1a);  c1b = fmaf(k0b.y, S[5], c1b);
            c2a = fmaf(q0a.y, S[1], c2a);  c2b = fmaf(q0b.y, S[5], c2b);
            c3a = fmaf(k1a.y, S[1], c3a);  c3b = fmaf(k1b.y, S[5], c3b);
            c4a = fmaf(q1a.y, S[1], c4a);  c4b = fmaf(q1b.y, S[5], c4b);
            c1a = fmaf(k0a.z, S[2], c1a);  c1b = fmaf(k0b.z, S[6], c1b);
            c2a = fmaf(q0a.z, S[2], c2a);  c2b = fmaf(q0b.z, S[6], c2b);
            c3a = fmaf(k1a.z, S[2], c3a);  c3b = fmaf(k1b.z, S[6], c3b);
            c4a = fmaf(q1a.z, S[2], c4a);  c4b = fmaf(q1b.z, S[6], c4b);
            c1a = fmaf(k0a.w, S[3], c1a);  c1b = fmaf(k0b.w, S[7], c1b);
            c2a = fmaf(q0a.w, S[3], c2a);  c2b = fmaf(q0b.w, S[7], c2b);
            c3a = fmaf(k1a.w, S[3], c3a);  c3b = fmaf(k1b.w, S[7], c3b);
            c4a = fmaf(q1a.w, S[3], c4a);  c4b = fmaf(q1b.w, S[7], c4b);

            float c1 = c1a + c1b, c2 = c2a + c2b, c3 = c3a + c3b, c4 = c4a + c4b;

            // one butterfly batch over 16 kgroups
#pragma unroll
            for (int m = 1; m <= 8; m <<= 1) {
                c1 += __shfl_xor_sync(0xffffffffu, c1, m);
                c2 += __shfl_xor_sync(0xffffffffu, c2, m);
                c3 += __shfl_xor_sync(0xffffffffu, c3, m);
                c4 += __shfl_xor_sync(0xffffffffu, c4, m);
            }

            const float eg0 = g0.x, b0 = g0.y, qk0 = g0.z;
            const float eg1 = g1.x, b1 = g1.y, qk1 = g1.z;

            const float d0 = fmaf(-eg0 * b0, c1, v0 * b0);       // delta_t
            const float o0 = fmaf(eg0, c2, qk0 * d0);
            const float r1p = fmaf(kk01, d0, eg0 * c3);           // k1 . S_t
            const float d1 = fmaf(-eg1 * b1, r1p, v1 * b1);       // delta_{t+1}
            const float r2p = fmaf(qk10, d0, eg0 * c4);           // q1 . S_t
            const float o1 = fmaf(eg1, r2p, qk1 * d1);

            if (kg == 0) {
                go[(size_t)tt * 2048 + obase]       = o0;
                go[(size_t)(tt + 1) * 2048 + obase] = o1;
            }

            const float a = eg1 * eg0;
            const float bc = eg1 * d0;
            S[0] = fmaf(k1a.x, d1, fmaf(k0a.x, bc, a * S[0]));
            S[1] = fmaf(k1a.y, d1, fmaf(k0a.y, bc, a * S[1]));
            S[2] = fmaf(k1a.z, d1, fmaf(k0a.z, bc, a * S[2]));
            S[3] = fmaf(k1a.w, d1, fmaf(k0a.w, bc, a * S[3]));
            S[4] = fmaf(k1b.x, d1, fmaf(k0b.x, bc, a * S[4]));
            S[5] = fmaf(k1b.y, d1, fmaf(k0b.y, bc, a * S[5]));
            S[6] = fmaf(k1b.z, d1, fmaf(k0b.z, bc, a * S[6]));
            S[7] = fmaf(k1b.w, d1, fmaf(k0b.w, bc, a * S[7]));
        }
    }
}

// ================= gated RMSNorm (emits tf32-rounded xn) =================
__global__ __launch_bounds__(128)
void rmsnorm_kernel(const float* __restrict__ go, const float* __restrict__ qkvz,
                    const float* __restrict__ nw, float* __restrict__ gxn) {
    const int t = blockIdx.x, vh = blockIdx.y, i = threadIdx.x;
    __shared__ float red[4];
    const float o = go[(size_t)t * 2048 + vh * 128 + i];
    const float z = qkvz[(size_t)t * QKVZN + (vh >> 1) * 768 + 512 + (vh & 1) * 128 + i];
    const float xf = o * (z / (1.f + expf(-z)));
    float v = xf * xf;
#pragma unroll
    for (int m = 16; m; m >>= 1) v += __shfl_xor_sync(0xffffffffu, v, m);
    if ((i & 31) == 0) red[i >> 5] = v;
    __syncthreads();
    const float s = red[0] + red[1] + red[2] + red[3];
    gxn[(size_t)t * 2048 + vh * 128 + i] =
        to_tf32(xf * rsqrtf(s * (1.f / 128.f) + 1e-6f) * nw[i]);
}

// ================= launch =================
extern "C" void kernel_launch(void* const* d_in, const int* in_sizes, int n_in,
                              void* d_out, int out_size) {
    const float* hs      = (const float*)d_in[0];
    const float* w_qkvz  = (const float*)d_in[1];
    const float* w_ba    = (const float*)d_in[2];
    const float* conv_w  = (const float*)d_in[3];
    const float* dt_bias = (const float*)d_in[4];
    const float* A_log   = (const float*)d_in[5];
    const float* norm_w  = (const float*)d_in[6];
    const float* w_out   = (const float*)d_in[7];
    float* out = (float*)d_out;

    float *p_qkvz, *p_ba, *p_v, *p_qn, *p_kn, *p_scal, *p_cross, *p_o, *p_xn;
    float *p_hsr, *p_wqr, *p_wor;
    cudaGetSymbolAddress((void**)&p_qkvz,  g_qkvz);
    cudaGetSymbolAddress((void**)&p_ba,    g_ba);
    cudaGetSymbolAddress((void**)&p_v,     g_v);
    cudaGetSymbolAddress((void**)&p_qn,    g_qn);
    cudaGetSymbolAddress((void**)&p_kn,    g_kn);
    cudaGetSymbolAddress((void**)&p_scal,  g_scal);
    cudaGetSymbolAddress((void**)&p_cross, g_cross);
    cudaGetSymbolAddress((void**)&p_o,     g_o);
    cudaGetSymbolAddress((void**)&p_xn,    g_xn);
    cudaGetSymbolAddress((void**)&p_hsr,   g_hsr);
    cudaGetSymbolAddress((void**)&p_wqr,   g_wqr);
    cudaGetSymbolAddress((void**)&p_wor,   g_wor);

    static int smem_set = 0;
    if (!smem_set) {
        cudaFuncSetAttribute(gemm_tf32_pipe, cudaFuncAttributeMaxDynamicSharedMemorySize,
                             GSTG * GSTF * 4);
        smem_set = 1;
    }

    // launch 0: ba projection + tf32 rounding (fused)
    pre_kernel<<<PREB, 256>>>(hs, w_ba, p_ba, (float4*)p_hsr, (float4*)p_wqr,
                              (float4*)p_wor, (const float4*)w_qkvz, (const float4*)w_out);
    // launch 1: qkvz projection [1024,6144]
    gemm_tf32_pipe<<<dim3(QKVZN / 128, TLEN / 128), 256, GSTG * GSTF * 4>>>(
        p_hsr, p_wqr, p_qkvz, QKVZN, HID);
    // launch 2: fused conv + silu + norms + gates + cross dots
    convprep_kernel<<<dim3(TLEN, NKH), 128>>>(p_qkvz, conv_w, p_ba, A_log, dt_bias,
                                              p_qn, p_kn, p_v, p_scal, p_cross);
    // launch 3: delta-rule scan, 2-step fused  (ncu captures launch index 3)
    scan_kernel<<<dim3(8, NVH), 256>>>(p_qn, p_kn, p_v, p_scal, p_cross, p_o);
    // launch 4: gated rmsnorm (tf32-rounded output)
    rmsnorm_kernel<<<dim3(TLEN, NVH), 128>>>(p_o, p_qkvz, norm_w, p_xn);
    // launch 5: output projection [1024,2048]
    gemm_tf32_pipe<<<dim3(HID / 128, TLEN / 128), 256, GSTG * GSTF * 4>>>(
        p_xn, p_wor, out, HID, HID);
}

// round 13
// speedup vs baseline: 1.1123x; 1.0254x over previous
#include <cuda_runtime.h>
#include <cstdint>
#include <math.h>

// ---------------- problem constants ----------------
#define TLEN 1024
#define HID  2048
#define NKH  8
#define NVH  16
#define QKVZN 6144
#define SCALE_Q 0.08838834764831845f   // 128^-0.5

// ---------------- device scratch (no allocation allowed) ----------------
__device__ float g_qkvz[TLEN * QKVZN];
__device__ float g_ba  [TLEN * 32];
__device__ float g_v   [TLEN * 2048];
__device__ float g_qn  [NKH * TLEN * 128];
__device__ float g_kn  [NKH * TLEN * 128];
__device__ float g_scal[NVH * TLEN * 4];
__device__ float g_o   [TLEN * 2048];
__device__ float g_xn  [TLEN * 2048];
__device__ float g_hsr [TLEN * HID];        // tf32-rounded hidden states
__device__ float g_wqr [QKVZN * HID];       // tf32-rounded w_qkvz
__device__ float g_wor [HID * HID];         // tf32-rounded w_out

// ---------------- helpers ----------------
__device__ __forceinline__ float to_tf32(float x) {
    float r;
    asm("cvt.rna.tf32.f32 %0, %1;" : "=f"(r) : "f"(x));
    return r;
}

__device__ __forceinline__ void cp16(void* smem_dst, const void* gmem_src) {
    uint32_t s = (uint32_t)__cvta_generic_to_shared(smem_dst);
    asm volatile("cp.async.cg.shared.global [%0], [%1], 16;\n" :: "r"(s), "l"(gmem_src));
}
#define CP_COMMIT()  asm volatile("cp.async.commit_group;\n")
#define CP_WAIT(n)   asm volatile("cp.async.wait_group %0;\n" :: "n"(n))

__device__ __forceinline__ void mma_tf32(float& d0, float& d1, float& d2, float& d3,
                                         uint32_t a0, uint32_t a1, uint32_t a2, uint32_t a3,
                                         uint32_t b0, uint32_t b1) {
    asm volatile(
        "mma.sync.aligned.m16n8k8.row.col.f32.tf32.tf32.f32 "
        "{%0,%1,%2,%3},{%4,%5,%6,%7},{%8,%9},{%0,%1,%2,%3};"
        : "+f"(d0), "+f"(d1), "+f"(d2), "+f"(d3)
        : "r"(a0), "r"(a1), "r"(a2), "r"(a3), "r"(b0), "r"(b1));
}

// ================= fused pre-pass: ba projection + tf32 rounding =================
#define NH4 (TLEN * HID / 4)
#define NQ4 (QKVZN * HID / 4)
#define NO4 (HID * HID / 4)
#define PREB 4608
__global__ __launch_bounds__(256)
void pre_kernel(const float* __restrict__ hs, const float* __restrict__ wba,
                float* __restrict__ ba_out,
                float4* __restrict__ hsr, float4* __restrict__ wqr,
                float4* __restrict__ wor, const float4* __restrict__ wq4,
                const float4* __restrict__ wo4) {
    const int tid = threadIdx.x;
    if (blockIdx.x < 1024) {
        const int t = blockIdx.x;
        const int n = tid >> 3, s = tid & 7;
        const float4* h4 = (const float4*)(hs + (size_t)t * HID + s * 256);
        const float4* w4 = (const float4*)(wba + (size_t)n * HID + s * 256);
        float acc = 0.f;
#pragma unroll 8
        for (int i = 0; i < 64; i++) {
            float4 a = h4[i], b = w4[i];
            acc += a.x * b.x + a.y * b.y + a.z * b.z + a.w * b.w;
        }
        acc += __shfl_xor_sync(0xffffffffu, acc, 1);
        acc += __shfl_xor_sync(0xffffffffu, acc, 2);
        acc += __shfl_xor_sync(0xffffffffu, acc, 4);
        if (s == 0) ba_out[t * 32 + n] = acc;
    } else {
        const float4* hs4 = (const float4*)hs;
        const int stride = (PREB - 1024) * 256;
        for (int i = (blockIdx.x - 1024) * 256 + tid; i < NH4 + NQ4 + NO4; i += stride) {
            float4 v;
            if (i < NH4) {
                v = hs4[i];
                v.x = to_tf32(v.x); v.y = to_tf32(v.y); v.z = to_tf32(v.z); v.w = to_tf32(v.w);
                hsr[i] = v;
            } else if (i < NH4 + NQ4) {
                v = wq4[i - NH4];
                v.x = to_tf32(v.x); v.y = to_tf32(v.y); v.z = to_tf32(v.z); v.w = to_tf32(v.w);
                wqr[i - NH4] = v;
            } else {
                v = wo4[i - NH4 - NQ4];
                v.x = to_tf32(v.x); v.y = to_tf32(v.y); v.z = to_tf32(v.z); v.w = to_tf32(v.w);
                wor[i - NH4 - NQ4] = v;
            }
        }
    }
}

// ================= tf32 GEMM (cp.async 4-stage, BK=16) — R9 proven =================
#define GSTG 4
#define GSTF 5120
__global__ __launch_bounds__(256, 2)
void gemm_tf32_pipe(const float* __restrict__ A, const float* __restrict__ B,
                    float* __restrict__ C, int N, int K) {
    extern __shared__ float sm[];   // GSTG * GSTF floats = 80KB

    const int tid  = threadIdx.x;
    const int warp = tid >> 5, lane = tid & 31;
    const int wm = warp & 1, wn = warp >> 1;
    const int bm = blockIdx.y * 128, bn = blockIdx.x * 128;
    const int r0 = tid >> 2, c4 = tid & 3;

    const float* Ab = A + (size_t)bm * K;
    const float* Bb = B + (size_t)bn * K;
    const int nk = K >> 4;

    float acc[4][4][4];
#pragma unroll
    for (int i = 0; i < 4; i++)
#pragma unroll
        for (int j = 0; j < 4; j++)
#pragma unroll
            for (int l = 0; l < 4; l++) acc[i][j][l] = 0.f;

    auto preload = [&](int kt) {
        const int k0 = (kt << 4) + c4 * 4;
        float* st = sm + (kt & 3) * GSTF;
        cp16(st + r0 * 20 + c4 * 4,                Ab + (size_t)r0 * K + k0);
        cp16(st + (r0 + 64) * 20 + c4 * 4,         Ab + (size_t)(r0 + 64) * K + k0);
        cp16(st + 2560 + r0 * 20 + c4 * 4,         Bb + (size_t)r0 * K + k0);
        cp16(st + 2560 + (r0 + 64) * 20 + c4 * 4,  Bb + (size_t)(r0 + 64) * K + k0);
    };

    preload(0); CP_COMMIT();
    preload(1); CP_COMMIT();
    preload(2); CP_COMMIT();

    for (int kt = 0; kt < nk; kt++) {
        CP_WAIT(2);
        __syncthreads();
        const float* sAb = sm + (kt & 3) * GSTF;
        const float* sBb = sAb + 2560;
#pragma unroll
        for (int ks = 0; ks < 2; ks++) {
            uint32_t af[4][4];
#pragma unroll
            for (int mt = 0; mt < 4; mt++) {
                const float* p = sAb + (wm * 64 + mt * 16 + (lane >> 2)) * 20 + ks * 8 + (lane & 3);
                af[mt][0] = __float_as_uint(p[0]);
                af[mt][1] = __float_as_uint(p[8 * 20]);
                af[mt][2] = __float_as_uint(p[4]);
                af[mt][3] = __float_as_uint(p[8 * 20 + 4]);
            }
            uint32_t bf[4][2];
#pragma unroll
            for (int nt = 0; nt < 4; nt++) {
                const float* p = sBb + (wn * 32 + nt * 8 + (lane >> 2)) * 20 + ks * 8 + (lane & 3);
                bf[nt][0] = __float_as_uint(p[0]);
                bf[nt][1] = __float_as_uint(p[4]);
            }
#pragma unroll
            for (int mt = 0; mt < 4; mt++)
#pragma unroll
                for (int nt = 0; nt < 4; nt++)
                    mma_tf32(acc[mt][nt][0], acc[mt][nt][1], acc[mt][nt][2], acc[mt][nt][3],
                             af[mt][0], af[mt][1], af[mt][2], af[mt][3],
                             bf[nt][0], bf[nt][1]);
        }
        if (kt + 3 < nk) preload(kt + 3);
        CP_COMMIT();
    }

#pragma unroll
    for (int mt = 0; mt < 4; mt++) {
#pragma unroll
        for (int nt = 0; nt < 4; nt++) {
            int row = bm + wm * 64 + mt * 16 + (lane >> 2);
            int col = bn + wn * 32 + nt * 8 + (lane & 3) * 2;
            C[(size_t)row * N + col]           = acc[mt][nt][0];
            C[(size_t)row * N + col + 1]       = acc[mt][nt][1];
            C[(size_t)(row + 8) * N + col]     = acc[mt][nt][2];
            C[(size_t)(row + 8) * N + col + 1] = acc[mt][nt][3];
        }
    }
}

// ================= fused conv1d+silu + l2-norm + gates =================
__global__ __launch_bounds__(128)
void convprep_kernel(const float* __restrict__ qkvz, const float* __restrict__ convw,
                     const float* __restrict__ gba, const float* __restrict__ A_log,
                     const float* __restrict__ dt_bias,
                     float* __restrict__ gqn, float* __restrict__ gkn,
                     float* __restrict__ gv, float* __restrict__ gscal) {
    const int t = blockIdx.x, kh = blockIdx.y, i = threadIdx.x;
    __shared__ float red[4];
    const int base = kh * 768;

    float xq[4], xk[4], xv0[4], xv1[4];
#pragma unroll
    for (int tau = 0; tau < 4; tau++) {
        const int tt = t - 3 + tau;
        const bool ok = (tt >= 0);
        const float* r = qkvz + (size_t)(ok ? tt : 0) * QKVZN + base;
        xq[tau]  = ok ? r[i]       : 0.f;
        xk[tau]  = ok ? r[128 + i] : 0.f;
        xv0[tau] = ok ? r[256 + i] : 0.f;
        xv1[tau] = ok ? r[384 + i] : 0.f;
    }
    const float4 wq  = *(const float4*)(convw + (size_t)(kh * 128 + i) * 4);
    const float4 wk  = *(const float4*)(convw + (size_t)(1024 + kh * 128 + i) * 4);
    const float4 wv0 = *(const float4*)(convw + (size_t)(2048 + (2 * kh) * 128 + i) * 4);
    const float4 wv1 = *(const float4*)(convw + (size_t)(2048 + (2 * kh + 1) * 128 + i) * 4);

    float q  = xq[0] * wq.x + xq[1] * wq.y + xq[2] * wq.z + xq[3] * wq.w;
    float k  = xk[0] * wk.x + xk[1] * wk.y + xk[2] * wk.z + xk[3] * wk.w;
    float v0 = xv0[0] * wv0.x + xv0[1] * wv0.y + xv0[2] * wv0.z + xv0[3] * wv0.w;
    float v1 = xv1[0] * wv1.x + xv1[1] * wv1.y + xv1[2] * wv1.z + xv1[3] * wv1.w;
    q  = q  / (1.f + expf(-q));
    k  = k  / (1.f + expf(-k));
    v0 = v0 / (1.f + expf(-v0));
    v1 = v1 / (1.f + expf(-v1));

    gv[(size_t)t * 2048 + (2 * kh) * 128 + i]     = v0;
    gv[(size_t)t * 2048 + (2 * kh + 1) * 128 + i] = v1;

    float v, s_qq, s_kk, s_qk;

    v = q * q;
#pragma unroll
    for (int m = 16; m; m >>= 1) v += __shfl_xor_sync(0xffffffffu, v, m);
    if ((i & 31) == 0) red[i >> 5] = v;
    __syncthreads();
    s_qq = red[0] + red[1] + red[2] + red[3];
    __syncthreads();

    v = k * k;
#pragma unroll
    for (int m = 16; m; m >>= 1) v += __shfl_xor_sync(0xffffffffu, v, m);
    if ((i & 31) == 0) red[i >> 5] = v;
    __syncthreads();
    s_kk = red[0] + red[1] + red[2] + red[3];
    __syncthreads();

    const float qn = q * rsqrtf(s_qq + 1e-6f) * SCALE_Q;
    const float kn = k * rsqrtf(s_kk + 1e-6f);
    gqn[((size_t)kh * TLEN + t) * 128 + i] = qn;
    gkn[((size_t)kh * TLEN + t) * 128 + i] = kn;

    v = qn * kn;
#pragma unroll
    for (int m = 16; m; m >>= 1) v += __shfl_xor_sync(0xffffffffu, v, m);
    if ((i & 31) == 0) red[i >> 5] = v;
    __syncthreads();
    s_qk = red[0] + red[1] + red[2] + red[3];

    if (i < 2) {
        const int vh = kh * 2 + i;
        const float b = gba[t * 32 + kh * 4 + i];
        const float a = gba[t * 32 + kh * 4 + 2 + i];
        const float beta = 1.f / (1.f + expf(-b));
        const float x = a + dt_bias[vh];
        const float sp = (x > 20.f) ? x : log1pf(expf(x));
        const float g = -expf(A_log[vh]) * sp;
        float4 sc;
        sc.x = expf(g); sc.y = beta; sc.z = s_qk; sc.w = 0.f;
        *(float4*)(gscal + ((size_t)vh * TLEN + t) * 4) = sc;
    }
}

// ================= gated delta-rule scan =================
// grid (16 vblocks, 16 heads) = 256 CTAs, 128 threads = 16 kgroups x 8 vcols,
// 2 CTAs per SM (independent barriers -> cross-CTA issue interleave).
// 16-slot ring, warp-per-slot prefetch, 4-step barrier cadence.
__global__ __launch_bounds__(128, 2)
void scan_kernel(const float* __restrict__ gqn, const float* __restrict__ gkn,
                 const float* __restrict__ gv, const float* __restrict__ gscal,
                 float* __restrict__ go) {
    const int vb = blockIdx.x;    // 0..15, 8 v-cols each
    const int vh = blockIdx.y;
    const int kh = vh >> 1;
    const int tid = threadIdx.x;
    const int kg = tid & 15;      // k group (8 k-slots each)
    const int vc = tid >> 4;      // v col within block (0..7)

    __shared__ __align__(16) float ring[16][272];  // k[128], q[128], v[8]@256, scal[4]@264

    const float* kbase = gkn + (size_t)kh * TLEN * 128;
    const float* qbase = gqn + (size_t)kh * TLEN * 128;
    const float* vbase = gv + vh * 128 + vb * 8;
    const float* sbase = gscal + (size_t)vh * TLEN * 4;

    float S[8];
#pragma unroll
    for (int i = 0; i < 8; i++) S[i] = 0.f;

    const int pw = tid >> 5, pl = tid & 31;   // 4 warps: warp pw owns slot t0+pw

    auto prefetch4 = [&](int t0) {
        const int tt = t0 + pw;
        if (tt < TLEN) {
            float* sl = ring[tt & 15];
            cp16(sl + pl * 4,       kbase + (size_t)tt * 128 + pl * 4);
            cp16(sl + 128 + pl * 4, qbase + (size_t)tt * 128 + pl * 4);
            if (pl < 2) cp16(sl + 256 + pl * 4, vbase + (size_t)tt * 2048 + pl * 4);
            if (pl == 2) cp16(sl + 264, sbase + (size_t)tt * 4);
        }
        CP_COMMIT();
    };

    prefetch4(0);
    prefetch4(4);
    prefetch4(8);

    const int obase = vh * 128 + vb * 8 + vc;

    for (int t = 0; t < TLEN; t += 4) {
        CP_WAIT(2);
        __syncthreads();
        prefetch4(t + 12);
#pragma unroll
        for (int u = 0; u < 4; u++) {
            const int tt = t + u;
            const float* sl = ring[tt & 15];
            const float4* kp = (const float4*)(sl + kg * 8);
            const float4* qp = (const float4*)(sl + 128 + kg * 8);
            const float4 k0 = kp[0], k1 = kp[1];
            const float4 q0 = qp[0], q1 = qp[1];

            const float4 sc = *(const float4*)(sl + 264);
            const float eg = sc.x, beta = sc.y, qk = sc.z;
            const float vt = sl[256 + vc];
            const float vtb = vt * beta;
            const float negb = -eg * beta;

            float r1a, r1b, r2a, r2b;
            r1a = k0.x * S[0];               r2a = q0.x * S[0];
            r1b = k1.x * S[4];               r2b = q1.x * S[4];
            r1a = fmaf(k0.y, S[1], r1a);     r2a = fmaf(q0.y, S[1], r2a);
            r1b = fmaf(k1.y, S[5], r1b);     r2b = fmaf(q1.y, S[5], r2b);
            r1a = fmaf(k0.z, S[2], r1a);     r2a = fmaf(q0.z, S[2], r2a);
            r1b = fmaf(k1.z, S[6], r1b);     r2b = fmaf(q1.z, S[6], r2b);
            r1a = fmaf(k0.w, S[3], r1a);     r2a = fmaf(q0.w, S[3], r2a);
            r1b = fmaf(k1.w, S[7], r1b);     r2b = fmaf(q1.w, S[7], r2b);

            float r1 = r1a + r1b;
            float r2 = r2a + r2b;

            r1 += __shfl_xor_sync(0xffffffffu, r1, 1);
            r2 += __shfl_xor_sync(0xffffffffu, r2, 1);
            r1 += __shfl_xor_sync(0xffffffffu, r1, 2);
            r2 += __shfl_xor_sync(0xffffffffu, r2, 2);
            r1 += __shfl_xor_sync(0xffffffffu, r1, 4);
            r2 += __shfl_xor_sync(0xffffffffu, r2, 4);
            r1 += __shfl_xor_sync(0xffffffffu, r1, 8);
            r2 += __shfl_xor_sync(0xffffffffu, r2, 8);

            float eS[8];
#pragma unroll
            for (int j = 0; j < 8; j++) eS[j] = eg * S[j];

            const float delta = fmaf(negb, r1, vtb);
            if (kg == 0) go[(size_t)tt * 2048 + obase] = fmaf(eg, r2, qk * delta);

            S[0] = fmaf(k0.x, delta, eS[0]);
            S[1] = fmaf(k0.y, delta, eS[1]);
            S[2] = fmaf(k0.z, delta, eS[2]);
            S[3] = fmaf(k0.w, delta, eS[3]);
            S[4] = fmaf(k1.x, delta, eS[4]);
            S[5] = fmaf(k1.y, delta, eS[5]);
            S[6] = fmaf(k1.z, delta, eS[6]);
            S[7] = fmaf(k1.w, delta, eS[7]);
        }
    }
}

// ================= gated RMSNorm (emits tf32-rounded xn) =================
__global__ __launch_bounds__(128)
void rmsnorm_kernel(const float* __restrict__ go, const float* __restrict__ qkvz,
                    const float* __restrict__ nw, float* __restrict__ gxn) {
    const int t = blockIdx.x, vh = blockIdx.y, i = threadIdx.x;
    __shared__ float red[4];
    const float o = go[(size_t)t * 2048 + vh * 128 + i];
    const float z = qkvz[(size_t)t * QKVZN + (vh >> 1) * 768 + 512 + (vh & 1) * 128 + i];
    const float xf = o * (z / (1.f + expf(-z)));
    float v = xf * xf;
#pragma unroll
    for (int m = 16; m; m >>= 1) v += __shfl_xor_sync(0xffffffffu, v, m);
    if ((i & 31) == 0) red[i >> 5] = v;
    __syncthreads();
    const float s = red[0] + red[1] + red[2] + red[3];
    gxn[(size_t)t * 2048 + vh * 128 + i] =
        to_tf32(xf * rsqrtf(s * (1.f / 128.f) + 1e-6f) * nw[i]);
}

// ================= launch =================
extern "C" void kernel_launch(void* const* d_in, const int* in_sizes, int n_in,
                              void* d_out, int out_size) {
    const float* hs      = (const float*)d_in[0];
    const float* w_qkvz  = (const float*)d_in[1];
    const float* w_ba    = (const float*)d_in[2];
    const float* conv_w  = (const float*)d_in[3];
    const float* dt_bias = (const float*)d_in[4];
    const float* A_log   = (const float*)d_in[5];
    const float* norm_w  = (const float*)d_in[6];
    const float* w_out   = (const float*)d_in[7];
    float* out = (float*)d_out;

    float *p_qkvz, *p_ba, *p_v, *p_qn, *p_kn, *p_scal, *p_o, *p_xn;
    float *p_hsr, *p_wqr, *p_wor;
    cudaGetSymbolAddress((void**)&p_qkvz, g_qkvz);
    cudaGetSymbolAddress((void**)&p_ba,   g_ba);
    cudaGetSymbolAddress((void**)&p_v,    g_v);
    cudaGetSymbolAddress((void**)&p_qn,   g_qn);
    cudaGetSymbolAddress((void**)&p_kn,   g_kn);
    cudaGetSymbolAddress((void**)&p_scal, g_scal);
    cudaGetSymbolAddress((void**)&p_o,    g_o);
    cudaGetSymbolAddress((void**)&p_xn,   g_xn);
    cudaGetSymbolAddress((void**)&p_hsr,  g_hsr);
    cudaGetSymbolAddress((void**)&p_wqr,  g_wqr);
    cudaGetSymbolAddress((void**)&p_wor,  g_wor);

    static int smem_set = 0;
    if (!smem_set) {
        cudaFuncSetAttribute(gemm_tf32_pipe, cudaFuncAttributeMaxDynamicSharedMemorySize,
                             GSTG * GSTF * 4);
        smem_set = 1;
    }

    // launch 0: ba projection + tf32 rounding (fused)
    pre_kernel<<<PREB, 256>>>(hs, w_ba, p_ba, (float4*)p_hsr, (float4*)p_wqr,
                              (float4*)p_wor, (const float4*)w_qkvz, (const float4*)w_out);
    // launch 1: qkvz projection [1024,6144]
    gemm_tf32_pipe<<<dim3(QKVZN / 128, TLEN / 128), 256, GSTG * GSTF * 4>>>(
        p_hsr, p_wqr, p_qkvz, QKVZN, HID);
    // launch 2: fused conv + silu + norms + gates
    convprep_kernel<<<dim3(TLEN, NKH), 128>>>(p_qkvz, conv_w, p_ba, A_log, dt_bias,
                                              p_qn, p_kn, p_v, p_scal);
    // launch 3: delta-rule scan, 2 CTAs/SM  (ncu captures launch index 3)
    scan_kernel<<<dim3(16, NVH), 128>>>(p_qn, p_kn, p_v, p_scal, p_o);
    // launch 4: gated rmsnorm (tf32-rounded output)
    rmsnorm_kernel<<<dim3(TLEN, NVH), 128>>>(p_o, p_qkvz, norm_w, p_xn);
    // launch 5: output projection [1024,2048]
    gemm_tf32_pipe<<<dim3(HID / 128, TLEN / 128), 256, GSTG * GSTF * 4>>>(
        p_xn, p_wor, out, HID, HID);
}